// round 9
// baseline (speedup 1.0000x reference)
#include <cuda_runtime.h>
#include <cuda_fp16.h>
#include <cstdint>

#define BB 2
#define TT 2048
#define DD 1024
#define HH 16
#define HDIM 64
#define QSTRIDE 8
#define MLPD 4096
#define NTOK (BB*TT)   // 4096

// ---------------- scratch ----------------
__device__ __half g_xn[(size_t)NTOK*DD];
__device__ __half g_qkv[(size_t)NTOK*3*DD];
__device__ __half g_o[(size_t)NTOK*DD];
__device__ __half g_h[(size_t)NTOK*MLPD];
__device__ float  g_x1[(size_t)NTOK*DD];
__device__ __half g_wh[(size_t)12*1024*1024];   // w_in(3M) w_out(1M) w1(4M) w2(4M)

// ---------------- helpers ----------------
__device__ __forceinline__ uint32_t smem_u32(const void* p) {
    uint32_t a;
    asm("{ .reg .u64 t; cvta.to.shared.u64 t, %1; cvt.u32.u64 %0, t; }" : "=r"(a) : "l"(p));
    return a;
}
#define CP_ASYNC16(dst, src) \
    asm volatile("cp.async.cg.shared.global [%0], [%1], 16;" :: "r"(dst), "l"(src) : "memory")
#define CP_COMMIT() asm volatile("cp.async.commit_group;" ::: "memory")
#define CP_WAIT0() asm volatile("cp.async.wait_group 0;" ::: "memory")
#define CP_WAIT1() asm volatile("cp.async.wait_group 1;" ::: "memory")
#define CP_WAIT2() asm volatile("cp.async.wait_group 2;" ::: "memory")

#define LDSM_X4(r0, r1, r2, r3, addr) \
    asm volatile("ldmatrix.sync.aligned.m8n8.x4.shared.b16 {%0,%1,%2,%3}, [%4];" \
        : "=r"(r0), "=r"(r1), "=r"(r2), "=r"(r3) : "r"(addr))

__device__ __forceinline__ void mma_f16(float* d, const uint32_t* a, const uint32_t* b) {
    asm volatile(
        "mma.sync.aligned.m16n8k16.row.col.f32.f16.f16.f32 "
        "{%0,%1,%2,%3}, {%4,%5,%6,%7}, {%8,%9}, {%0,%1,%2,%3};"
        : "+f"(d[0]), "+f"(d[1]), "+f"(d[2]), "+f"(d[3])
        : "r"(a[0]), "r"(a[1]), "r"(a[2]), "r"(a[3]), "r"(b[0]), "r"(b[1]));
}

// ---------------- fp16 mma GEMM: C = A @ W.T + bias (+epi) ----------------
// A [M,K] half row-major, W [N,K] half row-major. BM=128, BN=256, BK=32 halves.
// 256 threads = 8 warps 2(m)x4(n), each warp 64x64 via m16n8k16.
#define ROWH 40                         // padded halves per row
#define STG_A (128*ROWH*2)              // 10240 B
#define STG_BB (256*ROWH*2)             // 20480 B
#define STAGE_B (STG_A + STG_BB)        // 30720 B per stage
#define NSTG 4
#define SMEM_TOT (NSTG*STAGE_B)         // 122880 B -> 1 CTA/SM

template <int EPI>  // 0=bias->half, 1=bias+residual->float, 2=bias+GELU->half
__global__ void __launch_bounds__(256, 1)
hgemm(const __half* __restrict__ A, const __half* __restrict__ W,
      const float* __restrict__ bias, const float* __restrict__ res,
      void* __restrict__ Cv, int M, int N, int K)
{
    extern __shared__ __half smem[];
    uint32_t sbase = smem_u32(smem);
    int tid = threadIdx.x;
    int wid = tid >> 5, lane = tid & 31;
    int gp = lane >> 2, tc = lane & 3;
    int m0 = blockIdx.y * 128, n0 = blockIdx.x * 256;
    int wm = (wid & 1) * 64;       // warp m-offset
    int wn = (wid >> 1) * 64;      // warp n-offset

    // ldmatrix per-lane address components
    int a_row = lane & 15;
    int a_k8  = (lane >> 4) * 8;
    int b_grp = lane >> 3;
    int b_row = lane & 7;
    int b_nof = (b_grp >> 1) * 8 + b_row;
    int b_k8  = (b_grp & 1) * 8;

    float acc[4][8][4];
    #pragma unroll
    for (int i = 0; i < 4; i++)
        #pragma unroll
        for (int j = 0; j < 8; j++)
            #pragma unroll
            for (int k = 0; k < 4; k++) acc[i][j][k] = 0.f;

    const int KT = K >> 5;

    auto load_tile = [&](int s, int kt) {
        uint32_t sa = sbase + s * STAGE_B;
        uint32_t sb = sa + STG_A;
        const __half* Ag = A + (size_t)m0 * K + kt * 32;
        const __half* Wg = W + (size_t)n0 * K + kt * 32;
        #pragma unroll
        for (int i = 0; i < 2; i++) {
            int idx = i * 256 + tid;
            int row = idx >> 2, ch = idx & 3;
            CP_ASYNC16(sa + (row * ROWH + ch * 8) * 2, Ag + (size_t)row * K + ch * 8);
        }
        #pragma unroll
        for (int i = 0; i < 4; i++) {
            int idx = i * 256 + tid;
            int row = idx >> 2, ch = idx & 3;
            CP_ASYNC16(sb + (row * ROWH + ch * 8) * 2, Wg + (size_t)row * K + ch * 8);
        }
        CP_COMMIT();
    };

    load_tile(0, 0);
    load_tile(1, 1);
    load_tile(2, 2);

    for (int kt = 0; kt < KT; kt++) {
        if (kt + 2 < KT) { CP_WAIT2(); }
        else if (kt + 1 < KT) { CP_WAIT1(); }
        else { CP_WAIT0(); }
        __syncthreads();
        if (kt + 3 < KT) load_tile((kt + 3) % NSTG, kt + 3);

        uint32_t sa = sbase + (kt % NSTG) * STAGE_B;
        uint32_t sb = sa + STG_A;

        #pragma unroll
        for (int ks = 0; ks < 2; ks++) {
            uint32_t af[4][4], bf[4][4];
            #pragma unroll
            for (int mt = 0; mt < 4; mt++)
                LDSM_X4(af[mt][0], af[mt][1], af[mt][2], af[mt][3],
                        sa + ((wm + mt * 16 + a_row) * ROWH + ks * 16 + a_k8) * 2);
            #pragma unroll
            for (int p = 0; p < 4; p++)
                LDSM_X4(bf[p][0], bf[p][1], bf[p][2], bf[p][3],
                        sb + ((wn + p * 16 + b_nof) * ROWH + ks * 16 + b_k8) * 2);
            #pragma unroll
            for (int mt = 0; mt < 4; mt++)
                #pragma unroll
                for (int nt = 0; nt < 8; nt++)
                    mma_f16(acc[mt][nt], af[mt], &bf[nt >> 1][(nt & 1) * 2]);
        }
        __syncthreads();
    }

    // epilogue
    #pragma unroll
    for (int mt = 0; mt < 4; mt++) {
        int r0 = m0 + wm + mt * 16 + gp;
        #pragma unroll
        for (int nt = 0; nt < 8; nt++) {
            int c = n0 + wn + nt * 8 + 2 * tc;
            float bx = bias[c], by = bias[c + 1];
            #pragma unroll
            for (int half_ = 0; half_ < 2; half_++) {
                int r = r0 + half_ * 8;
                float vx = acc[mt][nt][half_ * 2 + 0] + bx;
                float vy = acc[mt][nt][half_ * 2 + 1] + by;
                size_t off = (size_t)r * N + c;
                if (EPI == 1) {
                    float2 rr = *(const float2*)(res + off);
                    vx += rr.x; vy += rr.y;
                    float2 o2; o2.x = vx; o2.y = vy;
                    *(float2*)((float*)Cv + off) = o2;
                } else {
                    if (EPI == 2) {
                        vx = 0.5f * vx * (1.0f + erff(vx * 0.70710678118f));
                        vy = 0.5f * vy * (1.0f + erff(vy * 0.70710678118f));
                    }
                    *(__half2*)((__half*)Cv + off) = __floats2half2_rn(vx, vy);
                }
            }
        }
    }
}

// ---------------- LayerNorm (float in, half out) ----------------
__global__ void ln_kernel(const float* __restrict__ x, const float* __restrict__ g,
                          const float* __restrict__ b, __half* __restrict__ out) {
    int row = blockIdx.x;
    int tid = threadIdx.x;
    const float4* xr = (const float4*)(x + (size_t)row * DD);
    float4 v = xr[tid];
    float s  = v.x + v.y + v.z + v.w;
    float ss = v.x*v.x + v.y*v.y + v.z*v.z + v.w*v.w;
    #pragma unroll
    for (int o = 16; o; o >>= 1) {
        s  += __shfl_xor_sync(0xffffffffu, s,  o);
        ss += __shfl_xor_sync(0xffffffffu, ss, o);
    }
    __shared__ float sm[8], sm2[8];
    int w = tid >> 5, l = tid & 31;
    if (l == 0) { sm[w] = s; sm2[w] = ss; }
    __syncthreads();
    float tot = 0.f, tot2 = 0.f;
    #pragma unroll
    for (int i = 0; i < 8; i++) { tot += sm[i]; tot2 += sm2[i]; }
    float mean = tot * (1.0f / DD);
    float var  = tot2 * (1.0f / DD) - mean * mean;
    float rstd = rsqrtf(var + 1e-5f);
    float4 gg = ((const float4*)g)[tid];
    float4 bb = ((const float4*)b)[tid];
    __half2 h0 = __floats2half2_rn((v.x - mean) * rstd * gg.x + bb.x,
                                   (v.y - mean) * rstd * gg.y + bb.y);
    __half2 h1 = __floats2half2_rn((v.z - mean) * rstd * gg.z + bb.z,
                                   (v.w - mean) * rstd * gg.w + bb.w);
    uint2 u;
    u.x = *(uint32_t*)&h0; u.y = *(uint32_t*)&h1;
    ((uint2*)(out + (size_t)row * DD))[tid] = u;
}

// ---------------- convert weights float -> half ----------------
__global__ void cvt_kernel(const float* __restrict__ in, __half* __restrict__ out, int n4) {
    int i = blockIdx.x * blockDim.x + threadIdx.x;
    if (i >= n4) return;
    float4 v = ((const float4*)in)[i];
    __half2 h0 = __floats2half2_rn(v.x, v.y);
    __half2 h1 = __floats2half2_rn(v.z, v.w);
    uint2 u; u.x = *(uint32_t*)&h0; u.y = *(uint32_t*)&h1;
    ((uint2*)out)[i] = u;
}

// ---------------- copy v -> o (half, raw 16B chunks) ----------------
__global__ void copy_v_kernel(const __half* __restrict__ qkv, __half* __restrict__ o) {
    int idx = blockIdx.x * blockDim.x + threadIdx.x;
    int row = idx >> 7, c8 = idx & 127;
    ((uint4*)o)[idx] = *(const uint4*)(qkv + (size_t)row * (3 * DD) + 2 * DD + c8 * 8);
}

// ---------------- global-row attention (half in, half out) ----------------
__global__ void __launch_bounds__(256)
attn_kernel(const __half* __restrict__ qkv, __half* __restrict__ o) {
    int bid = blockIdx.x;
    int qt = bid & 7;
    int h  = (bid >> 3) & 15;
    int b  = bid >> 7;

    __shared__ float Qs[32][68];
    __shared__ float Ks[32][68];
    __shared__ float Vs[32][68];
    __shared__ float S [32][36];

    int tid = threadIdx.x;
    int qi_ = tid >> 3, d8 = tid & 7;

    {
        int t = (qt * 32 + qi_) * QSTRIDE;
        uint4 u = *(const uint4*)(qkv + (size_t)(b * TT + t) * (3 * DD) + h * HDIM + d8 * 8);
        const __half2* hp = (const __half2*)&u;
        #pragma unroll
        for (int j = 0; j < 4; j++) {
            float2 f = __half22float2(hp[j]);
            Qs[qi_][d8 * 8 + j * 2]     = f.x * 0.125f;
            Qs[qi_][d8 * 8 + j * 2 + 1] = f.y * 0.125f;
        }
    }
    __syncthreads();

    int qi = tid >> 3, sl = tid & 7;
    float mrun = -1e30f, lrun = 0.f;
    float oacc[8] = {};

    for (int kt = 0; kt < TT / 32; kt++) {
        {
            size_t base = (size_t)(b * TT + kt * 32 + qi_) * (3 * DD) + h * HDIM + d8 * 8;
            uint4 uk = *(const uint4*)(qkv + base + DD);
            uint4 uv = *(const uint4*)(qkv + base + 2 * DD);
            const __half2* kp = (const __half2*)&uk;
            const __half2* vp = (const __half2*)&uv;
            #pragma unroll
            for (int j = 0; j < 4; j++) {
                float2 fk = __half22float2(kp[j]);
                float2 fv = __half22float2(vp[j]);
                Ks[qi_][d8 * 8 + j * 2] = fk.x;  Ks[qi_][d8 * 8 + j * 2 + 1] = fk.y;
                Vs[qi_][d8 * 8 + j * 2] = fv.x;  Vs[qi_][d8 * 8 + j * 2 + 1] = fv.y;
            }
        }
        __syncthreads();

        float s4[4] = {0.f, 0.f, 0.f, 0.f};
        #pragma unroll
        for (int d4 = 0; d4 < 16; d4++) {
            float4 qv = *(const float4*)&Qs[qi][d4 * 4];
            #pragma unroll
            for (int kj = 0; kj < 4; kj++) {
                float4 kv = *(const float4*)&Ks[kj * 8 + sl][d4 * 4];
                s4[kj] += qv.x * kv.x + qv.y * kv.y + qv.z * kv.z + qv.w * kv.w;
            }
        }
        float tmax = fmaxf(fmaxf(s4[0], s4[1]), fmaxf(s4[2], s4[3]));
        #pragma unroll
        for (int off = 4; off; off >>= 1)
            tmax = fmaxf(tmax, __shfl_xor_sync(0xffffffffu, tmax, off));
        float mnew = fmaxf(mrun, tmax);
        float psum = 0.f;
        #pragma unroll
        for (int kj = 0; kj < 4; kj++) {
            float p = __expf(s4[kj] - mnew);
            psum += p;
            S[qi][kj * 8 + sl] = p;
        }
        #pragma unroll
        for (int off = 4; off; off >>= 1)
            psum += __shfl_xor_sync(0xffffffffu, psum, off);
        float factor = __expf(mrun - mnew);
        lrun = lrun * factor + psum;
        mrun = mnew;
        __syncwarp();

        #pragma unroll
        for (int j = 0; j < 8; j++) oacc[j] *= factor;
        #pragma unroll
        for (int key = 0; key < 32; key++) {
            float p = S[qi][key];
            float4 v0 = *(const float4*)&Vs[key][sl * 8];
            float4 v1 = *(const float4*)&Vs[key][sl * 8 + 4];
            oacc[0] += p * v0.x; oacc[1] += p * v0.y;
            oacc[2] += p * v0.z; oacc[3] += p * v0.w;
            oacc[4] += p * v1.x; oacc[5] += p * v1.y;
            oacc[6] += p * v1.z; oacc[7] += p * v1.w;
        }
        __syncthreads();
    }

    float inv = 1.0f / lrun;
    int t = (qt * 32 + qi) * QSTRIDE;
    __half2 h0 = __floats2half2_rn(oacc[0] * inv, oacc[1] * inv);
    __half2 h1 = __floats2half2_rn(oacc[2] * inv, oacc[3] * inv);
    __half2 h2 = __floats2half2_rn(oacc[4] * inv, oacc[5] * inv);
    __half2 h3 = __floats2half2_rn(oacc[6] * inv, oacc[7] * inv);
    uint4 u;
    u.x = *(uint32_t*)&h0; u.y = *(uint32_t*)&h1;
    u.z = *(uint32_t*)&h2; u.w = *(uint32_t*)&h3;
    *(uint4*)(o + (size_t)(b * TT + t) * DD + h * HDIM + sl * 8) = u;
}

// ---------------- launch ----------------
extern "C" void kernel_launch(void* const* d_in, const int* in_sizes, int n_in,
                              void* d_out, int out_size) {
    const float* x     = (const float*)d_in[0];
    const float* w_in  = (const float*)d_in[1];
    const float* b_in  = (const float*)d_in[2];
    const float* w_out = (const float*)d_in[3];
    const float* b_out = (const float*)d_in[4];
    const float* w1    = (const float*)d_in[5];
    const float* b1    = (const float*)d_in[6];
    const float* w2    = (const float*)d_in[7];
    const float* b2    = (const float*)d_in[8];
    const float* ln1g  = (const float*)d_in[9];
    const float* ln1b  = (const float*)d_in[10];
    const float* ln2g  = (const float*)d_in[11];
    const float* ln2b  = (const float*)d_in[12];
    float* out = (float*)d_out;

    __half *xn, *qkv, *o, *hbuf, *wh;
    float *x1;
    cudaGetSymbolAddress((void**)&xn,   g_xn);
    cudaGetSymbolAddress((void**)&qkv,  g_qkv);
    cudaGetSymbolAddress((void**)&o,    g_o);
    cudaGetSymbolAddress((void**)&hbuf, g_h);
    cudaGetSymbolAddress((void**)&x1,   g_x1);
    cudaGetSymbolAddress((void**)&wh,   g_wh);
    __half* wh_in  = wh;
    __half* wh_out = wh + (size_t)3*1024*1024;
    __half* wh_1   = wh + (size_t)4*1024*1024;
    __half* wh_2   = wh + (size_t)8*1024*1024;

    cudaFuncSetAttribute(hgemm<0>, cudaFuncAttributeMaxDynamicSharedMemorySize, SMEM_TOT);
    cudaFuncSetAttribute(hgemm<1>, cudaFuncAttributeMaxDynamicSharedMemorySize, SMEM_TOT);
    cudaFuncSetAttribute(hgemm<2>, cudaFuncAttributeMaxDynamicSharedMemorySize, SMEM_TOT);

    // 0) convert weights to half
    cvt_kernel<<<(3*DD*DD/4 + 255)/256, 256>>>(w_in,  wh_in,  3*DD*DD/4);
    cvt_kernel<<<(DD*DD/4   + 255)/256, 256>>>(w_out, wh_out, DD*DD/4);
    cvt_kernel<<<(MLPD*DD/4 + 255)/256, 256>>>(w1,    wh_1,   MLPD*DD/4);
    cvt_kernel<<<(DD*MLPD/4 + 255)/256, 256>>>(w2,    wh_2,   DD*MLPD/4);

    // 1) LN1 -> half
    ln_kernel<<<NTOK, 256>>>(x, ln1g, ln1b, xn);
    // 2) qkv = xn @ w_in.T + b_in  (half out)
    hgemm<0><<<dim3(3*DD/256, NTOK/128), 256, SMEM_TOT>>>(xn, wh_in, b_in, nullptr, qkv, NTOK, 3*DD, DD);
    // 3) attention
    copy_v_kernel<<<NTOK*128/256, 256>>>(qkv, o);
    attn_kernel<<<BB*HH*8, 256>>>(qkv, o);
    // 4) x1 = o @ w_out.T + b_out + x  (float out)
    hgemm<1><<<dim3(DD/256, NTOK/128), 256, SMEM_TOT>>>(o, wh_out, b_out, x, x1, NTOK, DD, DD);
    // 5) LN2 -> half
    ln_kernel<<<NTOK, 256>>>(x1, ln2g, ln2b, xn);
    // 6) h = gelu(xn @ w1.T + b1)  (half out)
    hgemm<2><<<dim3(MLPD/256, NTOK/128), 256, SMEM_TOT>>>(xn, wh_1, b1, nullptr, hbuf, NTOK, MLPD, DD);
    // 7) out = h @ w2.T + b2 + x1  (float out)
    hgemm<1><<<dim3(DD/256, NTOK/128), 256, SMEM_TOT>>>(hbuf, wh_2, b2, x1, out, NTOK, DD, MLPD);
}

// round 10
// speedup vs baseline: 1.0712x; 1.0712x over previous
#include <cuda_runtime.h>
#include <cuda_fp16.h>
#include <cstdint>

#define BB 2
#define TT 2048
#define DD 1024
#define HH 16
#define HDIM 64
#define QSTRIDE 8
#define MLPD 4096
#define NTOK (BB*TT)   // 4096

// ---------------- scratch ----------------
__device__ __half g_xn[(size_t)NTOK*DD];
__device__ __half g_qkv[(size_t)NTOK*3*DD];
__device__ __half g_o[(size_t)NTOK*DD];
__device__ __half g_h[(size_t)NTOK*MLPD];
__device__ float  g_x1[(size_t)NTOK*DD];
__device__ __half g_wh[(size_t)12*1024*1024];   // w_in(3M) w_out(1M) w1(4M) w2(4M)

// ---------------- helpers ----------------
__device__ __forceinline__ uint32_t smem_u32(const void* p) {
    uint32_t a;
    asm("{ .reg .u64 t; cvta.to.shared.u64 t, %1; cvt.u32.u64 %0, t; }" : "=r"(a) : "l"(p));
    return a;
}
#define CP_ASYNC16(dst, src) \
    asm volatile("cp.async.cg.shared.global [%0], [%1], 16;" :: "r"(dst), "l"(src) : "memory")
#define CP_COMMIT() asm volatile("cp.async.commit_group;" ::: "memory")
#define CP_WAIT0() asm volatile("cp.async.wait_group 0;" ::: "memory")
#define CP_WAIT1() asm volatile("cp.async.wait_group 1;" ::: "memory")

#define LDSM_X4(r0, r1, r2, r3, addr) \
    asm volatile("ldmatrix.sync.aligned.m8n8.x4.shared.b16 {%0,%1,%2,%3}, [%4];" \
        : "=r"(r0), "=r"(r1), "=r"(r2), "=r"(r3) : "r"(addr))

__device__ __forceinline__ void mma_f16(float* d, const uint32_t* a, const uint32_t* b) {
    asm volatile(
        "mma.sync.aligned.m16n8k16.row.col.f32.f16.f16.f32 "
        "{%0,%1,%2,%3}, {%4,%5,%6,%7}, {%8,%9}, {%0,%1,%2,%3};"
        : "+f"(d[0]), "+f"(d[1]), "+f"(d[2]), "+f"(d[3])
        : "r"(a[0]), "r"(a[1]), "r"(a[2]), "r"(a[3]), "r"(b[0]), "r"(b[1]));
}

// ---------------- fp16 mma GEMM: C = A @ W.T + bias (+epi) ----------------
// A [M,K] half row-major, W [N,K] half row-major. BM=BN=128, BK=64 halves.
// 256 threads = 8 warps 2(m)x4(n), each warp 64x32 via m16n8k16. 2 CTA/SM.
#define ROWH 72                         // padded halves per 64-half row
#define STG_B (128*ROWH*2)              // 18432 B per operand block
#define STAGE_B (2*STG_B)               // 36864 B per stage
#define NSTG 3
#define SMEM_TOT (NSTG*STAGE_B)         // 110592 B -> 2 CTAs/SM

template <int EPI>  // 0=bias->half(+opt vout), 1=bias+residual->float, 2=bias+GELU->half
__global__ void __launch_bounds__(256, 2)
hgemm(const __half* __restrict__ A, const __half* __restrict__ W,
      const float* __restrict__ bias, const float* __restrict__ res,
      void* __restrict__ Cv, __half* __restrict__ vout, int M, int N, int K)
{
    extern __shared__ __half smem[];
    uint32_t sbase = smem_u32(smem);
    int tid = threadIdx.x;
    int wid = tid >> 5, lane = tid & 31;
    int gp = lane >> 2, tc = lane & 3;
    int m0 = blockIdx.y * 128, n0 = blockIdx.x * 128;
    int wm = (wid & 1) * 64;
    int wn = (wid >> 1) * 32;

    // ldmatrix per-lane address components
    int a_row = lane & 15;
    int a_k8  = (lane >> 4) * 8;
    int b_grp = lane >> 3;
    int b_row = lane & 7;
    int b_nof = (b_grp >> 1) * 8 + b_row;
    int b_k8  = (b_grp & 1) * 8;

    float acc[4][4][4];
    #pragma unroll
    for (int i = 0; i < 4; i++)
        #pragma unroll
        for (int j = 0; j < 4; j++)
            #pragma unroll
            for (int k = 0; k < 4; k++) acc[i][j][k] = 0.f;

    const int KT = K >> 6;

    auto load_tile = [&](int s, int kt) {
        uint32_t sa = sbase + s * STAGE_B;
        uint32_t sb = sa + STG_B;
        const __half* Ag = A + (size_t)m0 * K + kt * 64;
        const __half* Wg = W + (size_t)n0 * K + kt * 64;
        #pragma unroll
        for (int i = 0; i < 4; i++) {
            int idx = i * 256 + tid;
            int row = idx >> 3, ch = idx & 7;
            CP_ASYNC16(sa + (row * ROWH + ch * 8) * 2, Ag + (size_t)row * K + ch * 8);
        }
        #pragma unroll
        for (int i = 0; i < 4; i++) {
            int idx = i * 256 + tid;
            int row = idx >> 3, ch = idx & 7;
            CP_ASYNC16(sb + (row * ROWH + ch * 8) * 2, Wg + (size_t)row * K + ch * 8);
        }
        CP_COMMIT();
    };

    load_tile(0, 0);
    load_tile(1, 1);

    for (int kt = 0; kt < KT; kt++) {
        if (kt + 1 < KT) { CP_WAIT1(); } else { CP_WAIT0(); }
        __syncthreads();
        if (kt + 2 < KT) load_tile((kt + 2) % NSTG, kt + 2);

        uint32_t sa = sbase + (kt % NSTG) * STAGE_B;
        uint32_t sb = sa + STG_B;

        #pragma unroll
        for (int ks = 0; ks < 4; ks++) {
            uint32_t af[4][4], bf[2][4];
            #pragma unroll
            for (int mt = 0; mt < 4; mt++)
                LDSM_X4(af[mt][0], af[mt][1], af[mt][2], af[mt][3],
                        sa + ((wm + mt * 16 + a_row) * ROWH + ks * 16 + a_k8) * 2);
            #pragma unroll
            for (int p = 0; p < 2; p++)
                LDSM_X4(bf[p][0], bf[p][1], bf[p][2], bf[p][3],
                        sb + ((wn + p * 16 + b_nof) * ROWH + ks * 16 + b_k8) * 2);
            #pragma unroll
            for (int mt = 0; mt < 4; mt++)
                #pragma unroll
                for (int nt = 0; nt < 4; nt++)
                    mma_f16(acc[mt][nt], af[mt], &bf[nt >> 1][(nt & 1) * 2]);
        }
    }

    // epilogue
    #pragma unroll
    for (int mt = 0; mt < 4; mt++) {
        int r0 = m0 + wm + mt * 16 + gp;
        #pragma unroll
        for (int nt = 0; nt < 4; nt++) {
            int c = n0 + wn + nt * 8 + 2 * tc;
            float bx = bias[c], by = bias[c + 1];
            #pragma unroll
            for (int half_ = 0; half_ < 2; half_++) {
                int r = r0 + half_ * 8;
                float vx = acc[mt][nt][half_ * 2 + 0] + bx;
                float vy = acc[mt][nt][half_ * 2 + 1] + by;
                size_t off = (size_t)r * N + c;
                if (EPI == 1) {
                    float2 rr = *(const float2*)(res + off);
                    vx += rr.x; vy += rr.y;
                    float2 o2; o2.x = vx; o2.y = vy;
                    *(float2*)((float*)Cv + off) = o2;
                } else {
                    if (EPI == 2) {
                        vx = 0.5f * vx * (1.0f + erff(vx * 0.70710678118f));
                        vy = 0.5f * vy * (1.0f + erff(vy * 0.70710678118f));
                    }
                    __half2 hv = __floats2half2_rn(vx, vy);
                    *(__half2*)((__half*)Cv + off) = hv;
                    if (EPI == 0 && vout != nullptr && c >= 2 * DD) {
                        // fused v -> o copy (attention output = v for non-global rows)
                        *(__half2*)(vout + (size_t)r * DD + (c - 2 * DD)) = hv;
                    }
                }
            }
        }
    }
}

// ---------------- LayerNorm (float in, half out) ----------------
__global__ void ln_kernel(const float* __restrict__ x, const float* __restrict__ g,
                          const float* __restrict__ b, __half* __restrict__ out) {
    int row = blockIdx.x;
    int tid = threadIdx.x;
    const float4* xr = (const float4*)(x + (size_t)row * DD);
    float4 v = xr[tid];
    float s  = v.x + v.y + v.z + v.w;
    float ss = v.x*v.x + v.y*v.y + v.z*v.z + v.w*v.w;
    #pragma unroll
    for (int o = 16; o; o >>= 1) {
        s  += __shfl_xor_sync(0xffffffffu, s,  o);
        ss += __shfl_xor_sync(0xffffffffu, ss, o);
    }
    __shared__ float sm[8], sm2[8];
    int w = tid >> 5, l = tid & 31;
    if (l == 0) { sm[w] = s; sm2[w] = ss; }
    __syncthreads();
    float tot = 0.f, tot2 = 0.f;
    #pragma unroll
    for (int i = 0; i < 8; i++) { tot += sm[i]; tot2 += sm2[i]; }
    float mean = tot * (1.0f / DD);
    float var  = tot2 * (1.0f / DD) - mean * mean;
    float rstd = rsqrtf(var + 1e-5f);
    float4 gg = ((const float4*)g)[tid];
    float4 bb = ((const float4*)b)[tid];
    __half2 h0 = __floats2half2_rn((v.x - mean) * rstd * gg.x + bb.x,
                                   (v.y - mean) * rstd * gg.y + bb.y);
    __half2 h1 = __floats2half2_rn((v.z - mean) * rstd * gg.z + bb.z,
                                   (v.w - mean) * rstd * gg.w + bb.w);
    uint2 u;
    u.x = *(uint32_t*)&h0; u.y = *(uint32_t*)&h1;
    ((uint2*)(out + (size_t)row * DD))[tid] = u;
}

// ---------------- convert weights float -> half ----------------
__global__ void cvt_kernel(const float* __restrict__ in, __half* __restrict__ out, int n4) {
    int i = blockIdx.x * blockDim.x + threadIdx.x;
    if (i >= n4) return;
    float4 v = ((const float4*)in)[i];
    __half2 h0 = __floats2half2_rn(v.x, v.y);
    __half2 h1 = __floats2half2_rn(v.z, v.w);
    uint2 u; u.x = *(uint32_t*)&h0; u.y = *(uint32_t*)&h1;
    ((uint2*)out)[i] = u;
}

// ---------------- global-row attention (half in, half out) ----------------
__global__ void __launch_bounds__(256)
attn_kernel(const __half* __restrict__ qkv, __half* __restrict__ o) {
    int bid = blockIdx.x;
    int qt = bid & 7;
    int h  = (bid >> 3) & 15;
    int b  = bid >> 7;

    __shared__ float Qs[32][68];
    __shared__ float Ks[32][68];
    __shared__ float Vs[32][68];
    __shared__ float S [32][36];

    int tid = threadIdx.x;
    int qi_ = tid >> 3, d8 = tid & 7;

    {
        int t = (qt * 32 + qi_) * QSTRIDE;
        uint4 u = *(const uint4*)(qkv + (size_t)(b * TT + t) * (3 * DD) + h * HDIM + d8 * 8);
        const __half2* hp = (const __half2*)&u;
        #pragma unroll
        for (int j = 0; j < 4; j++) {
            float2 f = __half22float2(hp[j]);
            Qs[qi_][d8 * 8 + j * 2]     = f.x * 0.125f;
            Qs[qi_][d8 * 8 + j * 2 + 1] = f.y * 0.125f;
        }
    }
    __syncthreads();

    int qi = tid >> 3, sl = tid & 7;
    float mrun = -1e30f, lrun = 0.f;
    float oacc[8] = {};

    for (int kt = 0; kt < TT / 32; kt++) {
        {
            size_t base = (size_t)(b * TT + kt * 32 + qi_) * (3 * DD) + h * HDIM + d8 * 8;
            uint4 uk = *(const uint4*)(qkv + base + DD);
            uint4 uv = *(const uint4*)(qkv + base + 2 * DD);
            const __half2* kp = (const __half2*)&uk;
            const __half2* vp = (const __half2*)&uv;
            #pragma unroll
            for (int j = 0; j < 4; j++) {
                float2 fk = __half22float2(kp[j]);
                float2 fv = __half22float2(vp[j]);
                Ks[qi_][d8 * 8 + j * 2] = fk.x;  Ks[qi_][d8 * 8 + j * 2 + 1] = fk.y;
                Vs[qi_][d8 * 8 + j * 2] = fv.x;  Vs[qi_][d8 * 8 + j * 2 + 1] = fv.y;
            }
        }
        __syncthreads();

        float s4[4] = {0.f, 0.f, 0.f, 0.f};
        #pragma unroll
        for (int d4 = 0; d4 < 16; d4++) {
            float4 qv = *(const float4*)&Qs[qi][d4 * 4];
            #pragma unroll
            for (int kj = 0; kj < 4; kj++) {
                float4 kv = *(const float4*)&Ks[kj * 8 + sl][d4 * 4];
                s4[kj] += qv.x * kv.x + qv.y * kv.y + qv.z * kv.z + qv.w * kv.w;
            }
        }
        float tmax = fmaxf(fmaxf(s4[0], s4[1]), fmaxf(s4[2], s4[3]));
        #pragma unroll
        for (int off = 4; off; off >>= 1)
            tmax = fmaxf(tmax, __shfl_xor_sync(0xffffffffu, tmax, off));
        float mnew = fmaxf(mrun, tmax);
        float psum = 0.f;
        #pragma unroll
        for (int kj = 0; kj < 4; kj++) {
            float p = __expf(s4[kj] - mnew);
            psum += p;
            S[qi][kj * 8 + sl] = p;
        }
        #pragma unroll
        for (int off = 4; off; off >>= 1)
            psum += __shfl_xor_sync(0xffffffffu, psum, off);
        float factor = __expf(mrun - mnew);
        lrun = lrun * factor + psum;
        mrun = mnew;
        __syncwarp();

        #pragma unroll
        for (int j = 0; j < 8; j++) oacc[j] *= factor;
        #pragma unroll
        for (int key = 0; key < 32; key++) {
            float p = S[qi][key];
            float4 v0 = *(const float4*)&Vs[key][sl * 8];
            float4 v1 = *(const float4*)&Vs[key][sl * 8 + 4];
            oacc[0] += p * v0.x; oacc[1] += p * v0.y;
            oacc[2] += p * v0.z; oacc[3] += p * v0.w;
            oacc[4] += p * v1.x; oacc[5] += p * v1.y;
            oacc[6] += p * v1.z; oacc[7] += p * v1.w;
        }
        __syncthreads();
    }

    float inv = 1.0f / lrun;
    int t = (qt * 32 + qi) * QSTRIDE;
    __half2 h0 = __floats2half2_rn(oacc[0] * inv, oacc[1] * inv);
    __half2 h1 = __floats2half2_rn(oacc[2] * inv, oacc[3] * inv);
    __half2 h2 = __floats2half2_rn(oacc[4] * inv, oacc[5] * inv);
    __half2 h3 = __floats2half2_rn(oacc[6] * inv, oacc[7] * inv);
    uint4 u;
    u.x = *(uint32_t*)&h0; u.y = *(uint32_t*)&h1;
    u.z = *(uint32_t*)&h2; u.w = *(uint32_t*)&h3;
    *(uint4*)(o + (size_t)(b * TT + t) * DD + h * HDIM + sl * 8) = u;
}

// ---------------- launch ----------------
extern "C" void kernel_launch(void* const* d_in, const int* in_sizes, int n_in,
                              void* d_out, int out_size) {
    const float* x     = (const float*)d_in[0];
    const float* w_in  = (const float*)d_in[1];
    const float* b_in  = (const float*)d_in[2];
    const float* w_out = (const float*)d_in[3];
    const float* b_out = (const float*)d_in[4];
    const float* w1    = (const float*)d_in[5];
    const float* b1    = (const float*)d_in[6];
    const float* w2    = (const float*)d_in[7];
    const float* b2    = (const float*)d_in[8];
    const float* ln1g  = (const float*)d_in[9];
    const float* ln1b  = (const float*)d_in[10];
    const float* ln2g  = (const float*)d_in[11];
    const float* ln2b  = (const float*)d_in[12];
    float* out = (float*)d_out;

    __half *xn, *qkv, *o, *hbuf, *wh;
    float *x1;
    cudaGetSymbolAddress((void**)&xn,   g_xn);
    cudaGetSymbolAddress((void**)&qkv,  g_qkv);
    cudaGetSymbolAddress((void**)&o,    g_o);
    cudaGetSymbolAddress((void**)&hbuf, g_h);
    cudaGetSymbolAddress((void**)&x1,   g_x1);
    cudaGetSymbolAddress((void**)&wh,   g_wh);
    __half* wh_in  = wh;
    __half* wh_out = wh + (size_t)3*1024*1024;
    __half* wh_1   = wh + (size_t)4*1024*1024;
    __half* wh_2   = wh + (size_t)8*1024*1024;

    cudaFuncSetAttribute(hgemm<0>, cudaFuncAttributeMaxDynamicSharedMemorySize, SMEM_TOT);
    cudaFuncSetAttribute(hgemm<1>, cudaFuncAttributeMaxDynamicSharedMemorySize, SMEM_TOT);
    cudaFuncSetAttribute(hgemm<2>, cudaFuncAttributeMaxDynamicSharedMemorySize, SMEM_TOT);

    // 0) convert weights to half
    cvt_kernel<<<(3*DD*DD/4 + 255)/256, 256>>>(w_in,  wh_in,  3*DD*DD/4);
    cvt_kernel<<<(DD*DD/4   + 255)/256, 256>>>(w_out, wh_out, DD*DD/4);
    cvt_kernel<<<(MLPD*DD/4 + 255)/256, 256>>>(w1,    wh_1,   MLPD*DD/4);
    cvt_kernel<<<(DD*MLPD/4 + 255)/256, 256>>>(w2,    wh_2,   DD*MLPD/4);

    // 1) LN1 -> half
    ln_kernel<<<NTOK, 256>>>(x, ln1g, ln1b, xn);
    // 2) qkv = xn @ w_in.T + b_in  (half out; V columns also fused-copied into o)
    hgemm<0><<<dim3(3*DD/128, NTOK/128), 256, SMEM_TOT>>>(xn, wh_in, b_in, nullptr, qkv, o, NTOK, 3*DD, DD);
    // 3) attention (overwrites the 1/8 global rows of o)
    attn_kernel<<<BB*HH*8, 256>>>(qkv, o);
    // 4) x1 = o @ w_out.T + b_out + x  (float out)
    hgemm<1><<<dim3(DD/128, NTOK/128), 256, SMEM_TOT>>>(o, wh_out, b_out, x, x1, nullptr, NTOK, DD, DD);
    // 5) LN2 -> half
    ln_kernel<<<NTOK, 256>>>(x1, ln2g, ln2b, xn);
    // 6) h = gelu(xn @ w1.T + b1)  (half out)
    hgemm<2><<<dim3(MLPD/128, NTOK/128), 256, SMEM_TOT>>>(xn, wh_1, b1, nullptr, hbuf, nullptr, NTOK, MLPD, DD);
    // 7) out = h @ w2.T + b2 + x1  (float out)
    hgemm<1><<<dim3(DD/128, NTOK/128), 256, SMEM_TOT>>>(hbuf, wh_2, b2, x1, out, nullptr, NTOK, DD, MLPD);
}